// round 14
// baseline (speedup 1.0000x reference)
#include <cuda_runtime.h>
#include <cuda_fp16.h>
#include <cstdint>

#define SEQ 4096
#define DIM 768
#define NHEAD 12
#define DHEAD 64
#define POST_SCALE 19.595917942265423f  // sqrt(384)
#define EXP_OFS 8.0f                    // exp(s-8): cancels in softmax, avoids fp16 overflow
#define TCHUNK 1024                     // t-axis chunk (P chunk = 100.7MB, L2-resident)

// ---- device scratch (allocation-free rule) ----
__device__ __half g_x16[SEQ * DIM];
__device__ __half g_w[4 * DIM * DIM];          // packed Wq,Wk,Wv,Wo (fp16)
__device__ float  g_bqkv[3 * DIM];             // packed bq,bk,bv
__device__ __half g_QKV[3 * SEQ * DIM];        // Q,K,V planes (fp16)
__device__ __half g_Ah[SEQ * DIM];
__device__ float  g_acc[SEQ * DIM];            // fp32 PV accumulator (12.6MB)
__device__ __half g_P[(size_t)NHEAD * SEQ * TCHUNK];  // 100.7MB P chunk

// ---------------- PTX helpers ----------------
__device__ __forceinline__ void cp16(uint32_t dst, const void* src) {
    asm volatile("cp.async.cg.shared.global [%0], [%1], 16;\n" :: "r"(dst), "l"(src));
}
#define CP_COMMIT() asm volatile("cp.async.commit_group;\n")
#define CP_WAIT0()  asm volatile("cp.async.wait_group 0;\n")
#define CP_WAIT1()  asm volatile("cp.async.wait_group 1;\n")
#define CP_WAIT2()  asm volatile("cp.async.wait_group 2;\n")

#define LDSM4(R, a) asm volatile( \
    "ldmatrix.sync.aligned.m8n8.x4.shared.b16 {%0,%1,%2,%3}, [%4];" \
    : "=r"((R)[0]), "=r"((R)[1]), "=r"((R)[2]), "=r"((R)[3]) : "r"(a))
#define LDSM4T(R, a) asm volatile( \
    "ldmatrix.sync.aligned.m8n8.x4.trans.shared.b16 {%0,%1,%2,%3}, [%4];" \
    : "=r"((R)[0]), "=r"((R)[1]), "=r"((R)[2]), "=r"((R)[3]) : "r"(a))

__device__ __forceinline__ void mma16(float* c, const uint32_t* a, const uint32_t* b) {
    asm volatile(
        "mma.sync.aligned.m16n8k16.row.col.f32.f16.f16.f32 "
        "{%0,%1,%2,%3},{%4,%5,%6,%7},{%8,%9},{%0,%1,%2,%3};\n"
        : "+f"(c[0]), "+f"(c[1]), "+f"(c[2]), "+f"(c[3])
        : "r"(a[0]), "r"(a[1]), "r"(a[2]), "r"(a[3]), "r"(b[0]), "r"(b[1]));
}

// swizzled byte offset within a tile of 128B rows (8x16B chunks, chunk ^= row&7)
__device__ __forceinline__ uint32_t swz(int row, int ch) {
    return (uint32_t)(row * 128 + ((ch ^ (row & 7)) << 4));
}

// ---------------- merged fp32 -> fp16 convert + packing ----------------
#define NX2 (SEQ * DIM / 2)
#define NW2 (DIM * DIM / 2)
__global__ void cvt_all(
    const float* __restrict__ x,
    const float* __restrict__ Wq, const float* __restrict__ Wk,
    const float* __restrict__ Wv, const float* __restrict__ Wo,
    const float* __restrict__ bq, const float* __restrict__ bk,
    const float* __restrict__ bv,
    __half* __restrict__ x16, __half* __restrict__ wpk,
    float* __restrict__ bqkv)
{
    int i = blockIdx.x * blockDim.x + threadIdx.x;
    int stride = gridDim.x * blockDim.x;
    if (i < 3 * DIM) {
        bqkv[i] = (i < DIM) ? bq[i] : (i < 2 * DIM ? bk[i - DIM] : bv[i - 2 * DIM]);
    }
    __half2* xd = (__half2*)x16;
    __half2* wd = (__half2*)wpk;
    for (int j = i; j < NX2 + 4 * NW2; j += stride) {
        float2 v;
        if (j < NX2) {
            v = ((const float2*)x)[j];
            xd[j] = __floats2half2_rn(v.x, v.y);
        } else {
            int k = j - NX2;
            int seg = k / NW2, off = k - seg * NW2;
            const float* W = (seg == 0) ? Wq : (seg == 1) ? Wk : (seg == 2) ? Wv : Wo;
            v = ((const float2*)W)[off];
            wd[k] = __floats2half2_rn(v.x, v.y);
        }
    }
}

// ============================================================
// QKV fused (unchanged, proven): Y = X @ Wpk^T + bqkv.
// ============================================================
__global__ __launch_bounds__(256) void qkv16(
    const __half* __restrict__ X, const __half* __restrict__ W,
    const float* __restrict__ bias, __half* __restrict__ QKV)
{
    __shared__ __align__(16) unsigned char smbuf[49152];
    const uint32_t smb = (uint32_t)__cvta_generic_to_shared(smbuf);
    const int tid = threadIdx.x, lane = tid & 31, warp = tid >> 5;
    const int wm = warp >> 1, wn = warp & 1;
    const int m0 = blockIdx.y * 128, n0 = blockIdx.x * 64;
    const int g = lane >> 2, t4 = lane & 3;
    const int plane = n0 / DIM, ncol = n0 - plane * DIM;
    __half* Y = QKV + (size_t)plane * SEQ * DIM;

    float c[2][4][4];
#pragma unroll
    for (int mt = 0; mt < 2; mt++)
#pragma unroll
        for (int nt = 0; nt < 4; nt++)
#pragma unroll
            for (int r = 0; r < 4; r++) c[mt][nt][r] = 0.f;

    {
        uint32_t ab = smb, bb = smb + 16384;
#pragma unroll
        for (int i = 0; i < 4; i++) {
            int op = tid + i * 256; int row = op >> 3, ch = op & 7;
            cp16(ab + swz(row, ch), X + (size_t)(m0 + row) * DIM + ch * 8);
        }
#pragma unroll
        for (int i = 0; i < 2; i++) {
            int op = tid + i * 256; int row = op >> 3, ch = op & 7;
            cp16(bb + swz(row, ch), W + (size_t)(n0 + row) * DIM + ch * 8);
        }
        CP_COMMIT();
    }

    for (int it = 0; it < 12; it++) {
        if (it < 11) {
            int kt = (it + 1) * 64;
            uint32_t ab = smb + ((it + 1) & 1) * 24576, bb = ab + 16384;
#pragma unroll
            for (int i = 0; i < 4; i++) {
                int op = tid + i * 256; int row = op >> 3, ch = op & 7;
                cp16(ab + swz(row, ch), X + (size_t)(m0 + row) * DIM + kt + ch * 8);
            }
#pragma unroll
            for (int i = 0; i < 2; i++) {
                int op = tid + i * 256; int row = op >> 3, ch = op & 7;
                cp16(bb + swz(row, ch), W + (size_t)(n0 + row) * DIM + kt + ch * 8);
            }
            CP_COMMIT();
            CP_WAIT1();
        } else {
            CP_WAIT0();
        }
        __syncthreads();

        uint32_t ab = smb + (it & 1) * 24576, bb = ab + 16384;
#pragma unroll
        for (int ks = 0; ks < 4; ks++) {
            uint32_t a[2][4], b[2][4];
#pragma unroll
            for (int mt = 0; mt < 2; mt++) {
                int row = wm * 32 + mt * 16 + (lane & 15);
                int ch = ks * 2 + (lane >> 4);
                LDSM4(a[mt], ab + swz(row, ch));
            }
#pragma unroll
            for (int p = 0; p < 2; p++) {
                int row = wn * 32 + p * 16 + (lane & 7) + ((lane >> 4) << 3);
                int ch = ks * 2 + ((lane >> 3) & 1);
                LDSM4(b[p], bb + swz(row, ch));
            }
#pragma unroll
            for (int mt = 0; mt < 2; mt++) {
                mma16(c[mt][0], a[mt], &b[0][0]);
                mma16(c[mt][1], a[mt], &b[0][2]);
                mma16(c[mt][2], a[mt], &b[1][0]);
                mma16(c[mt][3], a[mt], &b[1][2]);
            }
        }
        __syncthreads();
    }

#pragma unroll
    for (int mt = 0; mt < 2; mt++)
#pragma unroll
        for (int nt = 0; nt < 4; nt++) {
            int cg = n0 + wn * 32 + nt * 8 + t4 * 2;
            float b0 = bias[cg], b1 = bias[cg + 1];
            int col = ncol + wn * 32 + nt * 8 + t4 * 2;
#pragma unroll
            for (int rh = 0; rh < 2; rh++) {
                int row = m0 + wm * 32 + mt * 16 + g + rh * 8;
                *(__half2*)(Y + (size_t)row * DIM + col) =
                    __floats2half2_rn(c[mt][nt][rh * 2] + b0, c[mt][nt][rh * 2 + 1] + b1);
            }
        }
}

// ============================================================
// Final linear (unchanged): out fp32 = A @ Wo^T + bo.
// ============================================================
__global__ __launch_bounds__(256) void oproj16(
    const __half* __restrict__ X, const __half* __restrict__ W,
    const float* __restrict__ bias, float* __restrict__ Y)
{
    __shared__ __align__(16) unsigned char smbuf[49152];
    const uint32_t smb = (uint32_t)__cvta_generic_to_shared(smbuf);
    const int tid = threadIdx.x, lane = tid & 31, warp = tid >> 5;
    const int wm = warp >> 1, wn = warp & 1;
    const int m0 = blockIdx.y * 128, n0 = blockIdx.x * 64;
    const int g = lane >> 2, t4 = lane & 3;

    float c[2][4][4];
#pragma unroll
    for (int mt = 0; mt < 2; mt++)
#pragma unroll
        for (int nt = 0; nt < 4; nt++)
#pragma unroll
            for (int r = 0; r < 4; r++) c[mt][nt][r] = 0.f;

    {
        uint32_t ab = smb, bb = smb + 16384;
#pragma unroll
        for (int i = 0; i < 4; i++) {
            int op = tid + i * 256; int row = op >> 3, ch = op & 7;
            cp16(ab + swz(row, ch), X + (size_t)(m0 + row) * DIM + ch * 8);
        }
#pragma unroll
        for (int i = 0; i < 2; i++) {
            int op = tid + i * 256; int row = op >> 3, ch = op & 7;
            cp16(bb + swz(row, ch), W + (size_t)(n0 + row) * DIM + ch * 8);
        }
        CP_COMMIT();
    }

    for (int it = 0; it < 12; it++) {
        if (it < 11) {
            int kt = (it + 1) * 64;
            uint32_t ab = smb + ((it + 1) & 1) * 24576, bb = ab + 16384;
#pragma unroll
            for (int i = 0; i < 4; i++) {
                int op = tid + i * 256; int row = op >> 3, ch = op & 7;
                cp16(ab + swz(row, ch), X + (size_t)(m0 + row) * DIM + kt + ch * 8);
            }
#pragma unroll
            for (int i = 0; i < 2; i++) {
                int op = tid + i * 256; int row = op >> 3, ch = op & 7;
                cp16(bb + swz(row, ch), W + (size_t)(n0 + row) * DIM + kt + ch * 8);
            }
            CP_COMMIT();
            CP_WAIT1();
        } else {
            CP_WAIT0();
        }
        __syncthreads();

        uint32_t ab = smb + (it & 1) * 24576, bb = ab + 16384;
#pragma unroll
        for (int ks = 0; ks < 4; ks++) {
            uint32_t a[2][4], b[2][4];
#pragma unroll
            for (int mt = 0; mt < 2; mt++) {
                int row = wm * 32 + mt * 16 + (lane & 15);
                int ch = ks * 2 + (lane >> 4);
                LDSM4(a[mt], ab + swz(row, ch));
            }
#pragma unroll
            for (int p = 0; p < 2; p++) {
                int row = wn * 32 + p * 16 + (lane & 7) + ((lane >> 4) << 3);
                int ch = ks * 2 + ((lane >> 3) & 1);
                LDSM4(b[p], bb + swz(row, ch));
            }
#pragma unroll
            for (int mt = 0; mt < 2; mt++) {
                mma16(c[mt][0], a[mt], &b[0][0]);
                mma16(c[mt][1], a[mt], &b[0][2]);
                mma16(c[mt][2], a[mt], &b[1][0]);
                mma16(c[mt][3], a[mt], &b[1][2]);
            }
        }
        __syncthreads();
    }

#pragma unroll
    for (int mt = 0; mt < 2; mt++)
#pragma unroll
        for (int nt = 0; nt < 4; nt++) {
            int col = n0 + wn * 32 + nt * 8 + t4 * 2;
            float b0 = bias[col], b1 = bias[col + 1];
#pragma unroll
            for (int rh = 0; rh < 2; rh++) {
                int row = m0 + wm * 32 + mt * 16 + g + rh * 8;
                float2 v = {c[mt][nt][rh * 2] + b0, c[mt][nt][rh * 2 + 1] + b1};
                *(float2*)(Y + (size_t)row * DIM + col) = v;
            }
        }
}

// ============================================================
// Scores + head-softmax (R11 winner, t-chunked):
// CTA 64x64, 512 thr = 4 head-groups x 4 warps (m32n32),
// fp16 exp(s-8) score buffer, 3 stages x 4 heads.
// P chunk layout: P[h][s][t_local], t_local stride TCHUNK.
// ============================================================
#define SC_BYTES  (12 * 64 * 64 * 2)      // 98304 fp16 exp-scores
#define STG_OFF   SC_BYTES
#define SC_SMEM   (SC_BYTES + 2 * 65536)  // 229376

__global__ __launch_bounds__(512) void scores16(
    const __half* __restrict__ Qh, const __half* __restrict__ Kh,
    __half* __restrict__ P, int t_base)
{
    extern __shared__ __align__(16) unsigned char sm[];
    __half* sc = (__half*)sm;
    const uint32_t smb = (uint32_t)__cvta_generic_to_shared(sm);
    const uint32_t stg = smb + STG_OFF;
    const int tid = threadIdx.x, lane = tid & 31, warp = tid >> 5;
    const int grp = warp >> 2;                 // head group 0..3
    const int ws = (warp >> 1) & 1, wt = warp & 1;  // 2x2 within group
    const int s0 = blockIdx.y * 64;
    const int t0l = blockIdx.x * 64;           // local (within chunk)
    const int t0g = t_base + t0l;              // global Q row
    const int g = lane >> 2, t4 = lane & 3;

#define LOAD_ST(st) do {                                                          \
        uint32_t buf = stg + ((st) & 1) * 65536;                                  \
        _Pragma("unroll")                                                         \
        for (int i = 0; i < 8; i++) {                                             \
            int op = tid + i * 512;                                               \
            int j = op >> 10, r = op & 1023;                                      \
            int hc = ((st) * 4 + j) * DHEAD;                                      \
            if (r < 512) {                                                        \
                int row = r >> 3, ch = r & 7;                                     \
                cp16(buf + j * 16384 + swz(row, ch),                              \
                     Kh + (size_t)(s0 + row) * DIM + hc + ch * 8);                \
            } else {                                                              \
                int r2 = r - 512; int row = r2 >> 3, ch = r2 & 7;                 \
                cp16(buf + j * 16384 + 8192 + swz(row, ch),                       \
                     Qh + (size_t)(t0g + row) * DIM + hc + ch * 8);               \
            }                                                                     \
        }                                                                         \
        CP_COMMIT();                                                              \
    } while (0)

#define COMPUTE_ST(st) do {                                                       \
        uint32_t kb = stg + ((st) & 1) * 65536 + grp * 16384;                     \
        uint32_t qb = kb + 8192;                                                  \
        int h = (st) * 4 + grp;                                                   \
        float acc[2][4][4];                                                       \
        _Pragma("unroll")                                                         \
        for (int mt = 0; mt < 2; mt++)                                            \
            _Pragma("unroll")                                                     \
            for (int nt = 0; nt < 4; nt++)                                        \
                _Pragma("unroll")                                                 \
                for (int r = 0; r < 4; r++) acc[mt][nt][r] = 0.f;                 \
        _Pragma("unroll")                                                         \
        for (int ks = 0; ks < 4; ks++) {                                          \
            uint32_t a[2][4], b[2][4];                                            \
            _Pragma("unroll")                                                     \
            for (int mt = 0; mt < 2; mt++) {                                      \
                int row = ws * 32 + mt * 16 + (lane & 15);                        \
                int ch = ks * 2 + (lane >> 4);                                    \
                LDSM4(a[mt], kb + swz(row, ch));                                  \
            }                                                                     \
            _Pragma("unroll")                                                     \
            for (int p = 0; p < 2; p++) {                                         \
                int row = wt * 32 + p * 16 + (lane & 7) + ((lane >> 4) << 3);     \
                int ch = ks * 2 + ((lane >> 3) & 1);                              \
                LDSM4(b[p], qb + swz(row, ch));                                   \
            }                                                                     \
            _Pragma("unroll")                                                     \
            for (int mt = 0; mt < 2; mt++) {                                      \
                mma16(acc[mt][0], a[mt], &b[0][0]);                               \
                mma16(acc[mt][1], a[mt], &b[0][2]);                               \
                mma16(acc[mt][2], a[mt], &b[1][0]);                               \
                mma16(acc[mt][3], a[mt], &b[1][2]);                               \
            }                                                                     \
        }                                                                         \
        _Pragma("unroll")                                                         \
        for (int mt = 0; mt < 2; mt++)                                            \
            _Pragma("unroll")                                                     \
            for (int nt = 0; nt < 4; nt++)                                        \
                _Pragma("unroll")                                                 \
                for (int rh = 0; rh < 2; rh++) {                                  \
                    int r = ws * 32 + mt * 16 + g + rh * 8;                       \
                    int col = wt * 32 + nt * 8 + t4 * 2;                          \
                    __half2 e = __floats2half2_rn(                                \
                        __expf(acc[mt][nt][rh * 2] - EXP_OFS),                    \
                        __expf(acc[mt][nt][rh * 2 + 1] - EXP_OFS));               \
                    *(__half2*)&sc[h * 4096 + r * 64 + (col ^ ((r & 7) << 3))] = e;\
                }                                                                 \
    } while (0)

    LOAD_ST(0);
    LOAD_ST(1);

    CP_WAIT1();
    __syncthreads();
    COMPUTE_ST(0);
    __syncthreads();           // buf0 consumed -> safe to refill
    LOAD_ST(2);

    CP_WAIT1();
    __syncthreads();
    COMPUTE_ST(1);

    CP_WAIT0();
    __syncthreads();
    COMPUTE_ST(2);
    __syncthreads();

    // softmax tail (R11 proven): sum 12 fp16 exps per (s, t-pair), scale, store
#pragma unroll
    for (int i = 0; i < 4; i++) {
        int p = tid + i * 512;           // 2048 pairs
        int s = p >> 5, tp = p & 31;
        int base = s * 64 + ((2 * tp) ^ ((s & 7) << 3));
        float ex[NHEAD], ey[NHEAD];
        float zx = 0.f, zy = 0.f;
#pragma unroll
        for (int h = 0; h < NHEAD; h++) {
            float2 v = __half22float2(*(const __half2*)&sc[h * 4096 + base]);
            ex[h] = v.x; ey[h] = v.y;
            zx += v.x; zy += v.y;
        }
        float ix = POST_SCALE / zx, iy = POST_SCALE / zy;
#pragma unroll
        for (int h = 0; h < NHEAD; h++) {
            *(__half2*)(P + ((size_t)h * SEQ + s0 + s) * TCHUNK + t0l + 2 * tp) =
                __floats2half2_rn(ex[h] * ix, ey[h] * iy);
        }
    }
#undef LOAD_ST
#undef COMPUTE_ST
}

// ============================================================
// PV chunked: accumulates over t-chunks into fp32 g_acc;
// last chunk emits fp16 Ah. BM=128, BN=64, BK=64, 3-stage
// ring (R11-proven mainloop), 256 threads, 3 CTAs/SM.
// ============================================================
#define PV_STAGE 24576
#define PV_SMEM  (3 * PV_STAGE)
#define NITER    (TCHUNK / 64)   // 16

__global__ __launch_bounds__(256, 3) void pv16(
    const __half* __restrict__ P, const __half* __restrict__ V,
    float* __restrict__ Acc, __half* __restrict__ Y, int chunk)
{
    extern __shared__ __align__(16) unsigned char pvsm[];
    const uint32_t smb = (uint32_t)__cvta_generic_to_shared(pvsm);
    const int tid = threadIdx.x, lane = tid & 31, warp = tid >> 5;
    const int wm = warp >> 1, wn = warp & 1;
    const int h = blockIdx.z;
    const int m0 = blockIdx.y * 128;
    const int g = lane >> 2, t4 = lane & 3;
    const int tb = chunk * TCHUNK;
    const __half* Ph = P + (size_t)h * SEQ * TCHUNK;

    float c[2][4][4];
#pragma unroll
    for (int mt = 0; mt < 2; mt++)
#pragma unroll
        for (int nt = 0; nt < 4; nt++)
#pragma unroll
            for (int r = 0; r < 4; r++) c[mt][nt][r] = 0.f;

#pragma unroll
    for (int st = 0; st < 2; st++) {
        int kt = st * 64;
        uint32_t ab = smb + st * PV_STAGE, bb = ab + 16384;
#pragma unroll
        for (int i = 0; i < 4; i++) {
            int op = tid + i * 256; int row = op >> 3, ch = op & 7;
            cp16(ab + swz(row, ch), Ph + (size_t)(m0 + row) * TCHUNK + kt + ch * 8);
        }
#pragma unroll
        for (int i = 0; i < 2; i++) {
            int op = tid + i * 256; int row = op >> 3, ch = op & 7;
            cp16(bb + swz(row, ch), V + (size_t)(tb + kt + row) * DIM + h * DHEAD + ch * 8);
        }
        CP_COMMIT();
    }

    for (int it = 0; it < NITER; it++) {
        int left = NITER - 1 - it;
        if (left >= 2) {
            int kt = (it + 2) * 64;
            uint32_t ab = smb + ((it + 2) % 3) * PV_STAGE, bb = ab + 16384;
#pragma unroll
            for (int i = 0; i < 4; i++) {
                int op = tid + i * 256; int row = op >> 3, ch = op & 7;
                cp16(ab + swz(row, ch), Ph + (size_t)(m0 + row) * TCHUNK + kt + ch * 8);
            }
#pragma unroll
            for (int i = 0; i < 2; i++) {
                int op = tid + i * 256; int row = op >> 3, ch = op & 7;
                cp16(bb + swz(row, ch), V + (size_t)(tb + kt + row) * DIM + h * DHEAD + ch * 8);
            }
            CP_COMMIT();
            CP_WAIT2();
        } else if (left == 1) {
            CP_WAIT1();
        } else {
            CP_WAIT0();
        }
        __syncthreads();

        uint32_t ab = smb + (it % 3) * PV_STAGE, bb = ab + 16384;
#pragma unroll
        for (int ks = 0; ks < 4; ks++) {
            uint32_t a[2][4], b[2][4];
#pragma unroll
            for (int mt = 0; mt < 2; mt++) {
                int row = wm * 32 + mt * 16 + (lane & 15);
                int ch = ks * 2 + (lane >> 4);
                LDSM4(a[mt], ab + swz(row, ch));
            }
#pragma unroll
            for (int p = 0; p < 2; p++) {
                int row = ks * 16 + (lane & 15);
                int ch = wn * 4 + p * 2 + (lane >> 4);
                LDSM4T(b[p], bb + swz(row, ch));
            }
#pragma unroll
            for (int mt = 0; mt < 2; mt++) {
                mma16(c[mt][0], a[mt], &b[0][0]);
                mma16(c[mt][1], a[mt], &b[0][2]);
                mma16(c[mt][2], a[mt], &b[1][0]);
                mma16(c[mt][3], a[mt], &b[1][2]);
            }
        }
        __syncthreads();
    }

    // epilogue: accumulate across chunks; last chunk -> fp16 Y
#pragma unroll
    for (int mt = 0; mt < 2; mt++)
#pragma unroll
        for (int nt = 0; nt < 4; nt++) {
            int col = h * DHEAD + wn * 32 + nt * 8 + t4 * 2;
#pragma unroll
            for (int rh = 0; rh < 2; rh++) {
                int row = m0 + wm * 32 + mt * 16 + g + rh * 8;
                float v0 = c[mt][nt][rh * 2], v1 = c[mt][nt][rh * 2 + 1];
                float* ap = Acc + (size_t)row * DIM + col;
                if (chunk > 0) {
                    float2 pr = *(const float2*)ap;
                    v0 += pr.x; v1 += pr.y;
                }
                if (chunk < (SEQ / TCHUNK) - 1) {
                    float2 o = {v0, v1};
                    *(float2*)ap = o;
                } else {
                    *(__half2*)(Y + (size_t)row * DIM + col) =
                        __floats2half2_rn(v0, v1);
                }
            }
        }
}

// ============================================================
extern "C" void kernel_launch(void* const* d_in, const int* in_sizes, int n_in,
                              void* d_out, int out_size)
{
    const float* x  = (const float*)d_in[0];
    const float* Wq = (const float*)d_in[1];
    const float* bq = (const float*)d_in[2];
    const float* Wk = (const float*)d_in[3];
    const float* bk = (const float*)d_in[4];
    const float* Wv = (const float*)d_in[5];
    const float* bv = (const float*)d_in[6];
    const float* Wo = (const float*)d_in[7];
    const float* bo = (const float*)d_in[8];
    float* out = (float*)d_out;

    __half *x16, *wpk, *QKV, *Ah, *P;
    float *bqkv, *acc;
    cudaGetSymbolAddress((void**)&x16, g_x16);
    cudaGetSymbolAddress((void**)&wpk, g_w);
    cudaGetSymbolAddress((void**)&bqkv, g_bqkv);
    cudaGetSymbolAddress((void**)&QKV, g_QKV);
    cudaGetSymbolAddress((void**)&Ah, g_Ah);
    cudaGetSymbolAddress((void**)&acc, g_acc);
    cudaGetSymbolAddress((void**)&P, g_P);

    cudaFuncSetAttribute(scores16, cudaFuncAttributeMaxDynamicSharedMemorySize, SC_SMEM);
    cudaFuncSetAttribute(pv16,     cudaFuncAttributeMaxDynamicSharedMemorySize, PV_SMEM);

    cvt_all<<<2048, 256>>>(x, Wq, Wk, Wv, Wo, bq, bk, bv, x16, wpk, bqkv);

    dim3 gqkv(3 * DIM / 64, SEQ / 128);
    qkv16<<<gqkv, 256>>>(x16, wpk, bqkv, QKV);

    const __half* Qh = QKV;
    const __half* Kh = QKV + (size_t)SEQ * DIM;
    const __half* Vh = QKV + (size_t)2 * SEQ * DIM;

    dim3 gsc(TCHUNK / 64, SEQ / 64);
    dim3 gpv(1, SEQ / 128, NHEAD);
    for (int c = 0; c < SEQ / TCHUNK; c++) {
        scores16<<<gsc, 512, SC_SMEM>>>(Qh, Kh, P, c * TCHUNK);
        pv16<<<gpv, 256, PV_SMEM>>>(P, Vh, acc, Ah, c);
    }

    dim3 glin(DIM / 64, SEQ / 128);
    oproj16<<<glin, 256>>>(Ah, wpk + (size_t)3 * DIM * DIM, bo, out);
}

// round 16
// speedup vs baseline: 1.0984x; 1.0984x over previous
#include <cuda_runtime.h>
#include <cuda_fp16.h>
#include <cstdint>

#define SEQ 4096
#define DIM 768
#define NHEAD 12
#define DHEAD 64
#define POST_SCALE 19.595917942265423f  // sqrt(384)
#define EXP_OFS 8.0f                    // exp(s-8): cancels in softmax, avoids fp16 overflow

// ---- device scratch (allocation-free rule) ----
__device__ __half g_x16[SEQ * DIM];
__device__ __half g_w[4 * DIM * DIM];          // packed Wq,Wk,Wv,Wo (fp16)
__device__ float  g_bqkv[3 * DIM];             // packed bq,bk,bv
__device__ __half g_QKV[3 * SEQ * DIM];        // Q,K,V planes (fp16)
__device__ __half g_Ah[SEQ * DIM];
__device__ __half g_P[(size_t)NHEAD * SEQ * SEQ];  // 402 MB

// ---------------- PTX helpers ----------------
__device__ __forceinline__ void cp16(uint32_t dst, const void* src) {
    asm volatile("cp.async.cg.shared.global [%0], [%1], 16;\n" :: "r"(dst), "l"(src));
}
#define CP_COMMIT() asm volatile("cp.async.commit_group;\n")
#define CP_WAIT0()  asm volatile("cp.async.wait_group 0;\n")
#define CP_WAIT1()  asm volatile("cp.async.wait_group 1;\n")
#define CP_WAIT2()  asm volatile("cp.async.wait_group 2;\n")

#define LDSM4(R, a) asm volatile( \
    "ldmatrix.sync.aligned.m8n8.x4.shared.b16 {%0,%1,%2,%3}, [%4];" \
    : "=r"((R)[0]), "=r"((R)[1]), "=r"((R)[2]), "=r"((R)[3]) : "r"(a))
#define LDSM4T(R, a) asm volatile( \
    "ldmatrix.sync.aligned.m8n8.x4.trans.shared.b16 {%0,%1,%2,%3}, [%4];" \
    : "=r"((R)[0]), "=r"((R)[1]), "=r"((R)[2]), "=r"((R)[3]) : "r"(a))

__device__ __forceinline__ void mma16(float* c, const uint32_t* a, const uint32_t* b) {
    asm volatile(
        "mma.sync.aligned.m16n8k16.row.col.f32.f16.f16.f32 "
        "{%0,%1,%2,%3},{%4,%5,%6,%7},{%8,%9},{%0,%1,%2,%3};\n"
        : "+f"(c[0]), "+f"(c[1]), "+f"(c[2]), "+f"(c[3])
        : "r"(a[0]), "r"(a[1]), "r"(a[2]), "r"(a[3]), "r"(b[0]), "r"(b[1]));
}

// swizzled byte offset within a tile of 128B rows (8x16B chunks, chunk ^= row&7)
__device__ __forceinline__ uint32_t swz(int row, int ch) {
    return (uint32_t)(row * 128 + ((ch ^ (row & 7)) << 4));
}

// ---------------- merged fp32 -> fp16 convert + packing ----------------
#define NX2 (SEQ * DIM / 2)
#define NW2 (DIM * DIM / 2)
__global__ void cvt_all(
    const float* __restrict__ x,
    const float* __restrict__ Wq, const float* __restrict__ Wk,
    const float* __restrict__ Wv, const float* __restrict__ Wo,
    const float* __restrict__ bq, const float* __restrict__ bk,
    const float* __restrict__ bv,
    __half* __restrict__ x16, __half* __restrict__ wpk,
    float* __restrict__ bqkv)
{
    int i = blockIdx.x * blockDim.x + threadIdx.x;
    int stride = gridDim.x * blockDim.x;
    if (i < 3 * DIM) {
        bqkv[i] = (i < DIM) ? bq[i] : (i < 2 * DIM ? bk[i - DIM] : bv[i - 2 * DIM]);
    }
    __half2* xd = (__half2*)x16;
    __half2* wd = (__half2*)wpk;
    for (int j = i; j < NX2 + 4 * NW2; j += stride) {
        float2 v;
        if (j < NX2) {
            v = ((const float2*)x)[j];
            xd[j] = __floats2half2_rn(v.x, v.y);
        } else {
            int k = j - NX2;
            int seg = k / NW2, off = k - seg * NW2;
            const float* W = (seg == 0) ? Wq : (seg == 1) ? Wk : (seg == 2) ? Wv : Wo;
            v = ((const float2*)W)[off];
            wd[k] = __floats2half2_rn(v.x, v.y);
        }
    }
}

// ============================================================
// QKV fused (proven): Y = X @ Wpk^T + bqkv.
// ============================================================
__global__ __launch_bounds__(256) void qkv16(
    const __half* __restrict__ X, const __half* __restrict__ W,
    const float* __restrict__ bias, __half* __restrict__ QKV)
{
    __shared__ __align__(16) unsigned char smbuf[49152];
    const uint32_t smb = (uint32_t)__cvta_generic_to_shared(smbuf);
    const int tid = threadIdx.x, lane = tid & 31, warp = tid >> 5;
    const int wm = warp >> 1, wn = warp & 1;
    const int m0 = blockIdx.y * 128, n0 = blockIdx.x * 64;
    const int g = lane >> 2, t4 = lane & 3;
    const int plane = n0 / DIM, ncol = n0 - plane * DIM;
    __half* Y = QKV + (size_t)plane * SEQ * DIM;

    float c[2][4][4];
#pragma unroll
    for (int mt = 0; mt < 2; mt++)
#pragma unroll
        for (int nt = 0; nt < 4; nt++)
#pragma unroll
            for (int r = 0; r < 4; r++) c[mt][nt][r] = 0.f;

    {
        uint32_t ab = smb, bb = smb + 16384;
#pragma unroll
        for (int i = 0; i < 4; i++) {
            int op = tid + i * 256; int row = op >> 3, ch = op & 7;
            cp16(ab + swz(row, ch), X + (size_t)(m0 + row) * DIM + ch * 8);
        }
#pragma unroll
        for (int i = 0; i < 2; i++) {
            int op = tid + i * 256; int row = op >> 3, ch = op & 7;
            cp16(bb + swz(row, ch), W + (size_t)(n0 + row) * DIM + ch * 8);
        }
        CP_COMMIT();
    }

    for (int it = 0; it < 12; it++) {
        if (it < 11) {
            int kt = (it + 1) * 64;
            uint32_t ab = smb + ((it + 1) & 1) * 24576, bb = ab + 16384;
#pragma unroll
            for (int i = 0; i < 4; i++) {
                int op = tid + i * 256; int row = op >> 3, ch = op & 7;
                cp16(ab + swz(row, ch), X + (size_t)(m0 + row) * DIM + kt + ch * 8);
            }
#pragma unroll
            for (int i = 0; i < 2; i++) {
                int op = tid + i * 256; int row = op >> 3, ch = op & 7;
                cp16(bb + swz(row, ch), W + (size_t)(n0 + row) * DIM + kt + ch * 8);
            }
            CP_COMMIT();
            CP_WAIT1();
        } else {
            CP_WAIT0();
        }
        __syncthreads();

        uint32_t ab = smb + (it & 1) * 24576, bb = ab + 16384;
#pragma unroll
        for (int ks = 0; ks < 4; ks++) {
            uint32_t a[2][4], b[2][4];
#pragma unroll
            for (int mt = 0; mt < 2; mt++) {
                int row = wm * 32 + mt * 16 + (lane & 15);
                int ch = ks * 2 + (lane >> 4);
                LDSM4(a[mt], ab + swz(row, ch));
            }
#pragma unroll
            for (int p = 0; p < 2; p++) {
                int row = wn * 32 + p * 16 + (lane & 7) + ((lane >> 4) << 3);
                int ch = ks * 2 + ((lane >> 3) & 1);
                LDSM4(b[p], bb + swz(row, ch));
            }
#pragma unroll
            for (int mt = 0; mt < 2; mt++) {
                mma16(c[mt][0], a[mt], &b[0][0]);
                mma16(c[mt][1], a[mt], &b[0][2]);
                mma16(c[mt][2], a[mt], &b[1][0]);
                mma16(c[mt][3], a[mt], &b[1][2]);
            }
        }
        __syncthreads();
    }

#pragma unroll
    for (int mt = 0; mt < 2; mt++)
#pragma unroll
        for (int nt = 0; nt < 4; nt++) {
            int cg = n0 + wn * 32 + nt * 8 + t4 * 2;
            float b0 = bias[cg], b1 = bias[cg + 1];
            int col = ncol + wn * 32 + nt * 8 + t4 * 2;
#pragma unroll
            for (int rh = 0; rh < 2; rh++) {
                int row = m0 + wm * 32 + mt * 16 + g + rh * 8;
                *(__half2*)(Y + (size_t)row * DIM + col) =
                    __floats2half2_rn(c[mt][nt][rh * 2] + b0, c[mt][nt][rh * 2 + 1] + b1);
            }
        }
}

// ============================================================
// Final linear (proven): out fp32 = A @ Wo^T + bo.
// ============================================================
__global__ __launch_bounds__(256) void oproj16(
    const __half* __restrict__ X, const __half* __restrict__ W,
    const float* __restrict__ bias, float* __restrict__ Y)
{
    __shared__ __align__(16) unsigned char smbuf[49152];
    const uint32_t smb = (uint32_t)__cvta_generic_to_shared(smbuf);
    const int tid = threadIdx.x, lane = tid & 31, warp = tid >> 5;
    const int wm = warp >> 1, wn = warp & 1;
    const int m0 = blockIdx.y * 128, n0 = blockIdx.x * 64;
    const int g = lane >> 2, t4 = lane & 3;

    float c[2][4][4];
#pragma unroll
    for (int mt = 0; mt < 2; mt++)
#pragma unroll
        for (int nt = 0; nt < 4; nt++)
#pragma unroll
            for (int r = 0; r < 4; r++) c[mt][nt][r] = 0.f;

    {
        uint32_t ab = smb, bb = smb + 16384;
#pragma unroll
        for (int i = 0; i < 4; i++) {
            int op = tid + i * 256; int row = op >> 3, ch = op & 7;
            cp16(ab + swz(row, ch), X + (size_t)(m0 + row) * DIM + ch * 8);
        }
#pragma unroll
        for (int i = 0; i < 2; i++) {
            int op = tid + i * 256; int row = op >> 3, ch = op & 7;
            cp16(bb + swz(row, ch), W + (size_t)(n0 + row) * DIM + ch * 8);
        }
        CP_COMMIT();
    }

    for (int it = 0; it < 12; it++) {
        if (it < 11) {
            int kt = (it + 1) * 64;
            uint32_t ab = smb + ((it + 1) & 1) * 24576, bb = ab + 16384;
#pragma unroll
            for (int i = 0; i < 4; i++) {
                int op = tid + i * 256; int row = op >> 3, ch = op & 7;
                cp16(ab + swz(row, ch), X + (size_t)(m0 + row) * DIM + kt + ch * 8);
            }
#pragma unroll
            for (int i = 0; i < 2; i++) {
                int op = tid + i * 256; int row = op >> 3, ch = op & 7;
                cp16(bb + swz(row, ch), W + (size_t)(n0 + row) * DIM + kt + ch * 8);
            }
            CP_COMMIT();
            CP_WAIT1();
        } else {
            CP_WAIT0();
        }
        __syncthreads();

        uint32_t ab = smb + (it & 1) * 24576, bb = ab + 16384;
#pragma unroll
        for (int ks = 0; ks < 4; ks++) {
            uint32_t a[2][4], b[2][4];
#pragma unroll
            for (int mt = 0; mt < 2; mt++) {
                int row = wm * 32 + mt * 16 + (lane & 15);
                int ch = ks * 2 + (lane >> 4);
                LDSM4(a[mt], ab + swz(row, ch));
            }
#pragma unroll
            for (int p = 0; p < 2; p++) {
                int row = wn * 32 + p * 16 + (lane & 7) + ((lane >> 4) << 3);
                int ch = ks * 2 + ((lane >> 3) & 1);
                LDSM4(b[p], bb + swz(row, ch));
            }
#pragma unroll
            for (int mt = 0; mt < 2; mt++) {
                mma16(c[mt][0], a[mt], &b[0][0]);
                mma16(c[mt][1], a[mt], &b[0][2]);
                mma16(c[mt][2], a[mt], &b[1][0]);
                mma16(c[mt][3], a[mt], &b[1][2]);
            }
        }
        __syncthreads();
    }

#pragma unroll
    for (int mt = 0; mt < 2; mt++)
#pragma unroll
        for (int nt = 0; nt < 4; nt++) {
            int col = n0 + wn * 32 + nt * 8 + t4 * 2;
            float b0 = bias[col], b1 = bias[col + 1];
#pragma unroll
            for (int rh = 0; rh < 2; rh++) {
                int row = m0 + wm * 32 + mt * 16 + g + rh * 8;
                float2 v = {c[mt][nt][rh * 2] + b0, c[mt][nt][rh * 2 + 1] + b1};
                *(float2*)(Y + (size_t)row * DIM + col) = v;
            }
        }
}

// ============================================================
// Scores + head-softmax (R11 champion):
// CTA 64x64, 512 thr = 4 head-groups x 4 warps (m32n32),
// fp16 exp(s-8) score buffer, 3 stages x 4 heads,
// register-held softmax tail.
// ============================================================
#define SC_BYTES  (12 * 64 * 64 * 2)      // 98304 fp16 exp-scores
#define STG_OFF   SC_BYTES
#define SC_SMEM   (SC_BYTES + 2 * 65536)  // 229376

__global__ __launch_bounds__(512) void scores16(
    const __half* __restrict__ Qh, const __half* __restrict__ Kh,
    __half* __restrict__ P)
{
    extern __shared__ __align__(16) unsigned char sm[];
    __half* sc = (__half*)sm;
    const uint32_t smb = (uint32_t)__cvta_generic_to_shared(sm);
    const uint32_t stg = smb + STG_OFF;
    const int tid = threadIdx.x, lane = tid & 31, warp = tid >> 5;
    const int grp = warp >> 2;                 // head group 0..3
    const int ws = (warp >> 1) & 1, wt = warp & 1;  // 2x2 within group
    const int s0 = blockIdx.y * 64, t0 = blockIdx.x * 64;
    const int g = lane >> 2, t4 = lane & 3;

#define LOAD_ST(st) do {                                                          \
        uint32_t buf = stg + ((st) & 1) * 65536;                                  \
        _Pragma("unroll")                                                         \
        for (int i = 0; i < 8; i++) {                                             \
            int op = tid + i * 512;                                               \
            int j = op >> 10, r = op & 1023;                                      \
            int hc = ((st) * 4 + j) * DHEAD;                                      \
            if (r < 512) {                                                        \
                int row = r >> 3, ch = r & 7;                                     \
                cp16(buf + j * 16384 + swz(row, ch),                              \
                     Kh + (size_t)(s0 + row) * DIM + hc + ch * 8);                \
            } else {                                                              \
                int r2 = r - 512; int row = r2 >> 3, ch = r2 & 7;                 \
                cp16(buf + j * 16384 + 8192 + swz(row, ch),                       \
                     Qh + (size_t)(t0 + row) * DIM + hc + ch * 8);                \
            }                                                                     \
        }                                                                         \
        CP_COMMIT();                                                              \
    } while (0)

#define COMPUTE_ST(st) do {                                                       \
        uint32_t kb = stg + ((st) & 1) * 65536 + grp * 16384;                     \
        uint32_t qb = kb + 8192;                                                  \
        int h = (st) * 4 + grp;                                                   \
        float acc[2][4][4];                                                       \
        _Pragma("unroll")                                                         \
        for (int mt = 0; mt < 2; mt++)                                            \
            _Pragma("unroll")                                                     \
            for (int nt = 0; nt < 4; nt++)                                        \
                _Pragma("unroll")                                                 \
                for (int r = 0; r < 4; r++) acc[mt][nt][r] = 0.f;                 \
        _Pragma("unroll")                                                         \
        for (int ks = 0; ks < 4; ks++) {                                          \
            uint32_t a[2][4], b[2][4];                                            \
            _Pragma("unroll")                                                     \
            for (int mt = 0; mt < 2; mt++) {                                      \
                int row = ws * 32 + mt * 16 + (lane & 15);                        \
                int ch = ks * 2 + (lane >> 4);                                    \
                LDSM4(a[mt], kb + swz(row, ch));                                  \
            }                                                                     \
            _Pragma("unroll")                                                     \
            for (int p = 0; p < 2; p++) {                                         \
                int row = wt * 32 + p * 16 + (lane & 7) + ((lane >> 4) << 3);     \
                int ch = ks * 2 + ((lane >> 3) & 1);                              \
                LDSM4(b[p], qb + swz(row, ch));                                   \
            }                                                                     \
            _Pragma("unroll")                                                     \
            for (int mt = 0; mt < 2; mt++) {                                      \
                mma16(acc[mt][0], a[mt], &b[0][0]);                               \
                mma16(acc[mt][1], a[mt], &b[0][2]);                               \
                mma16(acc[mt][2], a[mt], &b[1][0]);                               \
                mma16(acc[mt][3], a[mt], &b[1][2]);                               \
            }                                                                     \
        }                                                                         \
        _Pragma("unroll")                                                         \
        for (int mt = 0; mt < 2; mt++)                                            \
            _Pragma("unroll")                                                     \
            for (int nt = 0; nt < 4; nt++)                                        \
                _Pragma("unroll")                                                 \
                for (int rh = 0; rh < 2; rh++) {                                  \
                    int r = ws * 32 + mt * 16 + g + rh * 8;                       \
                    int col = wt * 32 + nt * 8 + t4 * 2;                          \
                    __half2 e = __floats2half2_rn(                                \
                        __expf(acc[mt][nt][rh * 2] - EXP_OFS),                    \
                        __expf(acc[mt][nt][rh * 2 + 1] - EXP_OFS));               \
                    *(__half2*)&sc[h * 4096 + r * 64 + (col ^ ((r & 7) << 3))] = e;\
                }                                                                 \
    } while (0)

    LOAD_ST(0);
    LOAD_ST(1);

    CP_WAIT1();
    __syncthreads();
    COMPUTE_ST(0);
    __syncthreads();           // buf0 consumed -> safe to refill
    LOAD_ST(2);

    CP_WAIT1();
    __syncthreads();
    COMPUTE_ST(1);

    CP_WAIT0();
    __syncthreads();
    COMPUTE_ST(2);
    __syncthreads();

    // softmax tail: sum 12 fp16 exps per (s, t-pair), scale, store
#pragma unroll
    for (int i = 0; i < 4; i++) {
        int p = tid + i * 512;           // 2048 pairs
        int s = p >> 5, tp = p & 31;
        int base = s * 64 + ((2 * tp) ^ ((s & 7) << 3));
        float ex[NHEAD], ey[NHEAD];
        float zx = 0.f, zy = 0.f;
#pragma unroll
        for (int h = 0; h < NHEAD; h++) {
            float2 v = __half22float2(*(const __half2*)&sc[h * 4096 + base]);
            ex[h] = v.x; ey[h] = v.y;
            zx += v.x; zy += v.y;
        }
        float ix = POST_SCALE / zx, iy = POST_SCALE / zy;
#pragma unroll
        for (int h = 0; h < NHEAD; h++) {
            *(__half2*)(P + ((size_t)h * SEQ + s0 + s) * SEQ + t0 + 2 * tp) =
                __floats2half2_rn(ex[h] * ix, ey[h] * iy);
        }
    }
#undef LOAD_ST
#undef COMPUTE_ST
}

// ============================================================
// PV (R11 champion, measured 84.4-85.2us): BM=128, BN=64,
// BK=64, 3-stage cp.async ring, 256 threads, 3 CTAs/SM hint.
// ============================================================
#define PV_STAGE 24576
#define PV_SMEM  (3 * PV_STAGE)

__global__ __launch_bounds__(256, 3) void pv16(
    const __half* __restrict__ P, const __half* __restrict__ V,
    __half* __restrict__ Y)
{
    extern __shared__ __align__(16) unsigned char pvsm[];
    const uint32_t smb = (uint32_t)__cvta_generic_to_shared(pvsm);
    const int tid = threadIdx.x, lane = tid & 31, warp = tid >> 5;
    const int wm = warp >> 1, wn = warp & 1;
    const int h = blockIdx.z;
    const int m0 = blockIdx.y * 128;
    const int g = lane >> 2, t4 = lane & 3;
    const __half* Ph = P + (size_t)h * SEQ * SEQ;

    float c[2][4][4];
#pragma unroll
    for (int mt = 0; mt < 2; mt++)
#pragma unroll
        for (int nt = 0; nt < 4; nt++)
#pragma unroll
            for (int r = 0; r < 4; r++) c[mt][nt][r] = 0.f;

#pragma unroll
    for (int st = 0; st < 2; st++) {
        int kt = st * 64;
        uint32_t ab = smb + st * PV_STAGE, bb = ab + 16384;
#pragma unroll
        for (int i = 0; i < 4; i++) {
            int op = tid + i * 256; int row = op >> 3, ch = op & 7;
            cp16(ab + swz(row, ch), Ph + (size_t)(m0 + row) * SEQ + kt + ch * 8);
        }
#pragma unroll
        for (int i = 0; i < 2; i++) {
            int op = tid + i * 256; int row = op >> 3, ch = op & 7;
            cp16(bb + swz(row, ch), V + (size_t)(kt + row) * DIM + h * DHEAD + ch * 8);
        }
        CP_COMMIT();
    }

    for (int it = 0; it < 64; it++) {
        int left = 63 - it;
        if (left >= 2) {
            int kt = (it + 2) * 64;
            uint32_t ab = smb + ((it + 2) % 3) * PV_STAGE, bb = ab + 16384;
#pragma unroll
            for (int i = 0; i < 4; i++) {
                int op = tid + i * 256; int row = op >> 3, ch = op & 7;
                cp16(ab + swz(row, ch), Ph + (size_t)(m0 + row) * SEQ + kt + ch * 8);
            }
#pragma unroll
            for (int i = 0; i < 2; i++) {
                int op = tid + i * 256; int row = op >> 3, ch = op & 7;
                cp16(bb + swz(row, ch), V + (size_t)(kt + row) * DIM + h * DHEAD + ch * 8);
            }
            CP_COMMIT();
            CP_WAIT2();
        } else if (left == 1) {
            CP_WAIT1();
        } else {
            CP_WAIT0();
        }
        __syncthreads();

        uint32_t ab = smb + (it % 3) * PV_STAGE, bb = ab + 16384;
#pragma unroll
        for (int ks = 0; ks < 4; ks++) {
            uint32_t a[2][4], b[2][4];
#pragma unroll
            for (int mt = 0; mt < 2; mt++) {
                int row = wm * 32 + mt * 16 + (lane & 15);
                int ch = ks * 2 + (lane >> 4);
                LDSM4(a[mt], ab + swz(row, ch));
            }
#pragma unroll
            for (int p = 0; p < 2; p++) {
                int row = ks * 16 + (lane & 15);
                int ch = wn * 4 + p * 2 + (lane >> 4);
                LDSM4T(b[p], bb + swz(row, ch));
            }
#pragma unroll
            for (int mt = 0; mt < 2; mt++) {
                mma16(c[mt][0], a[mt], &b[0][0]);
                mma16(c[mt][1], a[mt], &b[0][2]);
                mma16(c[mt][2], a[mt], &b[1][0]);
                mma16(c[mt][3], a[mt], &b[1][2]);
            }
        }
        __syncthreads();
    }

#pragma unroll
    for (int mt = 0; mt < 2; mt++)
#pragma unroll
        for (int nt = 0; nt < 4; nt++) {
            int col = h * DHEAD + wn * 32 + nt * 8 + t4 * 2;
#pragma unroll
            for (int rh = 0; rh < 2; rh++) {
                int row = m0 + wm * 32 + mt * 16 + g + rh * 8;
                *(__half2*)(Y + (size_t)row * DIM + col) =
                    __floats2half2_rn(c[mt][nt][rh * 2], c[mt][nt][rh * 2 + 1]);
            }
        }
}

// ============================================================
extern "C" void kernel_launch(void* const* d_in, const int* in_sizes, int n_in,
                              void* d_out, int out_size)
{
    const float* x  = (const float*)d_in[0];
    const float* Wq = (const float*)d_in[1];
    const float* bq = (const float*)d_in[2];
    const float* Wk = (const float*)d_in[3];
    const float* bk = (const float*)d_in[4];
    const float* Wv = (const float*)d_in[5];
    const float* bv = (const float*)d_in[6];
    const float* Wo = (const float*)d_in[7];
    const float* bo = (const float*)d_in[8];
    float* out = (float*)d_out;

    __half *x16, *wpk, *QKV, *Ah, *P;
    float* bqkv;
    cudaGetSymbolAddress((void**)&x16, g_x16);
    cudaGetSymbolAddress((void**)&wpk, g_w);
    cudaGetSymbolAddress((void**)&bqkv, g_bqkv);
    cudaGetSymbolAddress((void**)&QKV, g_QKV);
    cudaGetSymbolAddress((void**)&Ah, g_Ah);
    cudaGetSymbolAddress((void**)&P, g_P);

    cudaFuncSetAttribute(scores16, cudaFuncAttributeMaxDynamicSharedMemorySize, SC_SMEM);
    cudaFuncSetAttribute(pv16,     cudaFuncAttributeMaxDynamicSharedMemorySize, PV_SMEM);

    cvt_all<<<2048, 256>>>(x, Wq, Wk, Wv, Wo, bq, bk, bv, x16, wpk, bqkv);

    dim3 gqkv(3 * DIM / 64, SEQ / 128);
    qkv16<<<gqkv, 256>>>(x16, wpk, bqkv, QKV);

    const __half* Qh = QKV;
    const __half* Kh = QKV + (size_t)SEQ * DIM;
    const __half* Vh = QKV + (size_t)2 * SEQ * DIM;

    dim3 gsc(SEQ / 64, SEQ / 64);
    scores16<<<gsc, 512, SC_SMEM>>>(Qh, Kh, P);

    dim3 gpv(1, SEQ / 128, NHEAD);
    pv16<<<gpv, 256, PV_SMEM>>>(P, Vh, Ah);

    dim3 glin(DIM / 64, SEQ / 128);
    oproj16<<<glin, 256>>>(Ah, wpk + (size_t)3 * DIM * DIM, bo, out);
}

// round 17
// speedup vs baseline: 1.1213x; 1.0209x over previous
#include <cuda_runtime.h>
#include <cuda_fp16.h>
#include <cstdint>

#define SEQ 4096
#define DIM 768
#define NHEAD 12
#define DHEAD 64
#define POST_SCALE 19.595917942265423f  // sqrt(384)
#define EXP_OFS 8.0f                    // exp(s-8): cancels in softmax, avoids fp16 overflow

// ---- device scratch (allocation-free rule) ----
__device__ __half g_x16[SEQ * DIM];
__device__ __half g_w[4 * DIM * DIM];          // packed Wq,Wk,Wv,Wo (fp16)
__device__ float  g_bqkv[3 * DIM];             // packed bq,bk,bv
__device__ __half g_QKV[3 * SEQ * DIM];        // Q,K,V planes (fp16)
__device__ __half g_Ah[SEQ * DIM];
__device__ __half g_P[(size_t)NHEAD * SEQ * SEQ];  // 402 MB

// ---------------- PTX helpers ----------------
__device__ __forceinline__ void cp16(uint32_t dst, const void* src) {
    asm volatile("cp.async.cg.shared.global [%0], [%1], 16;\n" :: "r"(dst), "l"(src));
}
#define CP_COMMIT() asm volatile("cp.async.commit_group;\n")
#define CP_WAIT0()  asm volatile("cp.async.wait_group 0;\n")
#define CP_WAIT1()  asm volatile("cp.async.wait_group 1;\n")
#define CP_WAIT2()  asm volatile("cp.async.wait_group 2;\n")

#define LDSM4(R, a) asm volatile( \
    "ldmatrix.sync.aligned.m8n8.x4.shared.b16 {%0,%1,%2,%3}, [%4];" \
    : "=r"((R)[0]), "=r"((R)[1]), "=r"((R)[2]), "=r"((R)[3]) : "r"(a))
#define LDSM4T(R, a) asm volatile( \
    "ldmatrix.sync.aligned.m8n8.x4.trans.shared.b16 {%0,%1,%2,%3}, [%4];" \
    : "=r"((R)[0]), "=r"((R)[1]), "=r"((R)[2]), "=r"((R)[3]) : "r"(a))

__device__ __forceinline__ void mma16(float* c, const uint32_t* a, const uint32_t* b) {
    asm volatile(
        "mma.sync.aligned.m16n8k16.row.col.f32.f16.f16.f32 "
        "{%0,%1,%2,%3},{%4,%5,%6,%7},{%8,%9},{%0,%1,%2,%3};\n"
        : "+f"(c[0]), "+f"(c[1]), "+f"(c[2]), "+f"(c[3])
        : "r"(a[0]), "r"(a[1]), "r"(a[2]), "r"(a[3]), "r"(b[0]), "r"(b[1]));
}

// swizzled byte offset within a tile of 128B rows (8x16B chunks, chunk ^= row&7)
__device__ __forceinline__ uint32_t swz(int row, int ch) {
    return (uint32_t)(row * 128 + ((ch ^ (row & 7)) << 4));
}

// ---------------- merged fp32 -> fp16 convert + packing ----------------
#define NX2 (SEQ * DIM / 2)
#define NW2 (DIM * DIM / 2)
__global__ void cvt_all(
    const float* __restrict__ x,
    const float* __restrict__ Wq, const float* __restrict__ Wk,
    const float* __restrict__ Wv, const float* __restrict__ Wo,
    const float* __restrict__ bq, const float* __restrict__ bk,
    const float* __restrict__ bv,
    __half* __restrict__ x16, __half* __restrict__ wpk,
    float* __restrict__ bqkv)
{
    int i = blockIdx.x * blockDim.x + threadIdx.x;
    int stride = gridDim.x * blockDim.x;
    if (i < 3 * DIM) {
        bqkv[i] = (i < DIM) ? bq[i] : (i < 2 * DIM ? bk[i - DIM] : bv[i - 2 * DIM]);
    }
    __half2* xd = (__half2*)x16;
    __half2* wd = (__half2*)wpk;
    for (int j = i; j < NX2 + 4 * NW2; j += stride) {
        float2 v;
        if (j < NX2) {
            v = ((const float2*)x)[j];
            xd[j] = __floats2half2_rn(v.x, v.y);
        } else {
            int k = j - NX2;
            int seg = k / NW2, off = k - seg * NW2;
            const float* W = (seg == 0) ? Wq : (seg == 1) ? Wk : (seg == 2) ? Wv : Wo;
            v = ((const float2*)W)[off];
            wd[k] = __floats2half2_rn(v.x, v.y);
        }
    }
}

// ============================================================
// Linear, BN=128: Y = X @ W^T + bias.  BM=128 BN=128 BK=64,
// 256 threads, 8 warps (4m x 2n), warp tile 32x64.
// Halves X L2 re-reads vs BN=64. F16OUT: plane-split half out
// (QKV); else fp32 out (oproj).
// ============================================================
#define LN_STAGE 32768                 // 16KB A + 16KB B
#define LN_SMEM  (2 * LN_STAGE)        // 64KB

template<bool F16OUT>
__global__ __launch_bounds__(256) void linear128(
    const __half* __restrict__ X, const __half* __restrict__ W,
    const float* __restrict__ bias, void* __restrict__ Yv)
{
    extern __shared__ __align__(16) unsigned char lnsm[];
    const uint32_t smb = (uint32_t)__cvta_generic_to_shared(lnsm);
    const int tid = threadIdx.x, lane = tid & 31, warp = tid >> 5;
    const int wm = warp >> 1, wn = warp & 1;
    const int m0 = blockIdx.y * 128, n0 = blockIdx.x * 128;
    const int g = lane >> 2, t4 = lane & 3;
    // BN=128 divides DIM=768 -> a block never straddles planes
    const int plane = F16OUT ? (n0 / DIM) : 0;
    __half* Yh = F16OUT ? ((__half*)Yv + (size_t)plane * SEQ * DIM) : nullptr;
    float*  Yf = F16OUT ? nullptr : (float*)Yv;

    float c[2][8][4];
#pragma unroll
    for (int mt = 0; mt < 2; mt++)
#pragma unroll
        for (int nt = 0; nt < 8; nt++)
#pragma unroll
            for (int r = 0; r < 4; r++) c[mt][nt][r] = 0.f;

    {
        uint32_t ab = smb, bb = smb + 16384;
#pragma unroll
        for (int i = 0; i < 4; i++) {
            int op = tid + i * 256; int row = op >> 3, ch = op & 7;
            cp16(ab + swz(row, ch), X + (size_t)(m0 + row) * DIM + ch * 8);
        }
#pragma unroll
        for (int i = 0; i < 4; i++) {
            int op = tid + i * 256; int row = op >> 3, ch = op & 7;
            cp16(bb + swz(row, ch), W + (size_t)(n0 + row) * DIM + ch * 8);
        }
        CP_COMMIT();
    }

    for (int it = 0; it < 12; it++) {
        if (it < 11) {
            int kt = (it + 1) * 64;
            uint32_t ab = smb + ((it + 1) & 1) * LN_STAGE, bb = ab + 16384;
#pragma unroll
            for (int i = 0; i < 4; i++) {
                int op = tid + i * 256; int row = op >> 3, ch = op & 7;
                cp16(ab + swz(row, ch), X + (size_t)(m0 + row) * DIM + kt + ch * 8);
            }
#pragma unroll
            for (int i = 0; i < 4; i++) {
                int op = tid + i * 256; int row = op >> 3, ch = op & 7;
                cp16(bb + swz(row, ch), W + (size_t)(n0 + row) * DIM + kt + ch * 8);
            }
            CP_COMMIT();
            CP_WAIT1();
        } else {
            CP_WAIT0();
        }
        __syncthreads();

        uint32_t ab = smb + (it & 1) * LN_STAGE, bb = ab + 16384;
#pragma unroll
        for (int ks = 0; ks < 4; ks++) {
            uint32_t a[2][4], b[4][4];
#pragma unroll
            for (int mt = 0; mt < 2; mt++) {
                int row = wm * 32 + mt * 16 + (lane & 15);
                int ch = ks * 2 + (lane >> 4);
                LDSM4(a[mt], ab + swz(row, ch));
            }
#pragma unroll
            for (int p = 0; p < 4; p++) {
                int row = wn * 64 + p * 16 + (lane & 7) + ((lane >> 4) << 3);
                int ch = ks * 2 + ((lane >> 3) & 1);
                LDSM4(b[p], bb + swz(row, ch));
            }
#pragma unroll
            for (int mt = 0; mt < 2; mt++)
#pragma unroll
                for (int nt = 0; nt < 8; nt++)
                    mma16(c[mt][nt], a[mt], &b[nt >> 1][(nt & 1) * 2]);
        }
        __syncthreads();
    }

#pragma unroll
    for (int mt = 0; mt < 2; mt++)
#pragma unroll
        for (int nt = 0; nt < 8; nt++) {
            int cg = n0 + wn * 64 + nt * 8 + t4 * 2;
            float b0 = bias[cg], b1 = bias[cg + 1];
            int col = cg - plane * DIM;
#pragma unroll
            for (int rh = 0; rh < 2; rh++) {
                int row = m0 + wm * 32 + mt * 16 + g + rh * 8;
                float v0 = c[mt][nt][rh * 2] + b0;
                float v1 = c[mt][nt][rh * 2 + 1] + b1;
                if (F16OUT) {
                    *(__half2*)(Yh + (size_t)row * DIM + col) =
                        __floats2half2_rn(v0, v1);
                } else {
                    float2 v = {v0, v1};
                    *(float2*)(Yf + (size_t)row * DIM + col) = v;
                }
            }
        }
}

// ============================================================
// Scores + head-softmax (R11 champion, unchanged):
// CTA 64x64, 512 thr = 4 head-groups x 4 warps (m32n32),
// fp16 exp(s-8) score buffer, 3 stages x 4 heads,
// register-held softmax tail.
// ============================================================
#define SC_BYTES  (12 * 64 * 64 * 2)      // 98304 fp16 exp-scores
#define STG_OFF   SC_BYTES
#define SC_SMEM   (SC_BYTES + 2 * 65536)  // 229376

__global__ __launch_bounds__(512) void scores16(
    const __half* __restrict__ Qh, const __half* __restrict__ Kh,
    __half* __restrict__ P)
{
    extern __shared__ __align__(16) unsigned char sm[];
    __half* sc = (__half*)sm;
    const uint32_t smb = (uint32_t)__cvta_generic_to_shared(sm);
    const uint32_t stg = smb + STG_OFF;
    const int tid = threadIdx.x, lane = tid & 31, warp = tid >> 5;
    const int grp = warp >> 2;                 // head group 0..3
    const int ws = (warp >> 1) & 1, wt = warp & 1;  // 2x2 within group
    const int s0 = blockIdx.y * 64, t0 = blockIdx.x * 64;
    const int g = lane >> 2, t4 = lane & 3;

#define LOAD_ST(st) do {                                                          \
        uint32_t buf = stg + ((st) & 1) * 65536;                                  \
        _Pragma("unroll")                                                         \
        for (int i = 0; i < 8; i++) {                                             \
            int op = tid + i * 512;                                               \
            int j = op >> 10, r = op & 1023;                                      \
            int hc = ((st) * 4 + j) * DHEAD;                                      \
            if (r < 512) {                                                        \
                int row = r >> 3, ch = r & 7;                                     \
                cp16(buf + j * 16384 + swz(row, ch),                              \
                     Kh + (size_t)(s0 + row) * DIM + hc + ch * 8);                \
            } else {                                                              \
                int r2 = r - 512; int row = r2 >> 3, ch = r2 & 7;                 \
                cp16(buf + j * 16384 + 8192 + swz(row, ch),                       \
                     Qh + (size_t)(t0 + row) * DIM + hc + ch * 8);                \
            }                                                                     \
        }                                                                         \
        CP_COMMIT();                                                              \
    } while (0)

#define COMPUTE_ST(st) do {                                                       \
        uint32_t kb = stg + ((st) & 1) * 65536 + grp * 16384;                     \
        uint32_t qb = kb + 8192;                                                  \
        int h = (st) * 4 + grp;                                                   \
        float acc[2][4][4];                                                       \
        _Pragma("unroll")                                                         \
        for (int mt = 0; mt < 2; mt++)                                            \
            _Pragma("unroll")                                                     \
            for (int nt = 0; nt < 4; nt++)                                        \
                _Pragma("unroll")                                                 \
                for (int r = 0; r < 4; r++) acc[mt][nt][r] = 0.f;                 \
        _Pragma("unroll")                                                         \
        for (int ks = 0; ks < 4; ks++) {                                          \
            uint32_t a[2][4], b[2][4];                                            \
            _Pragma("unroll")                                                     \
            for (int mt = 0; mt < 2; mt++) {                                      \
                int row = ws * 32 + mt * 16 + (lane & 15);                        \
                int ch = ks * 2 + (lane >> 4);                                    \
                LDSM4(a[mt], kb + swz(row, ch));                                  \
            }                                                                     \
            _Pragma("unroll")                                                     \
            for (int p = 0; p < 2; p++) {                                         \
                int row = wt * 32 + p * 16 + (lane & 7) + ((lane >> 4) << 3);     \
                int ch = ks * 2 + ((lane >> 3) & 1);                              \
                LDSM4(b[p], qb + swz(row, ch));                                   \
            }                                                                     \
            _Pragma("unroll")                                                     \
            for (int mt = 0; mt < 2; mt++) {                                      \
                mma16(acc[mt][0], a[mt], &b[0][0]);                               \
                mma16(acc[mt][1], a[mt], &b[0][2]);                               \
                mma16(acc[mt][2], a[mt], &b[1][0]);                               \
                mma16(acc[mt][3], a[mt], &b[1][2]);                               \
            }                                                                     \
        }                                                                         \
        _Pragma("unroll")                                                         \
        for (int mt = 0; mt < 2; mt++)                                            \
            _Pragma("unroll")                                                     \
            for (int nt = 0; nt < 4; nt++)                                        \
                _Pragma("unroll")                                                 \
                for (int rh = 0; rh < 2; rh++) {                                  \
                    int r = ws * 32 + mt * 16 + g + rh * 8;                       \
                    int col = wt * 32 + nt * 8 + t4 * 2;                          \
                    __half2 e = __floats2half2_rn(                                \
                        __expf(acc[mt][nt][rh * 2] - EXP_OFS),                    \
                        __expf(acc[mt][nt][rh * 2 + 1] - EXP_OFS));               \
                    *(__half2*)&sc[h * 4096 + r * 64 + (col ^ ((r & 7) << 3))] = e;\
                }                                                                 \
    } while (0)

    LOAD_ST(0);
    LOAD_ST(1);

    CP_WAIT1();
    __syncthreads();
    COMPUTE_ST(0);
    __syncthreads();           // buf0 consumed -> safe to refill
    LOAD_ST(2);

    CP_WAIT1();
    __syncthreads();
    COMPUTE_ST(1);

    CP_WAIT0();
    __syncthreads();
    COMPUTE_ST(2);
    __syncthreads();

    // softmax tail: sum 12 fp16 exps per (s, t-pair), scale, store
#pragma unroll
    for (int i = 0; i < 4; i++) {
        int p = tid + i * 512;           // 2048 pairs
        int s = p >> 5, tp = p & 31;
        int base = s * 64 + ((2 * tp) ^ ((s & 7) << 3));
        float ex[NHEAD], ey[NHEAD];
        float zx = 0.f, zy = 0.f;
#pragma unroll
        for (int h = 0; h < NHEAD; h++) {
            float2 v = __half22float2(*(const __half2*)&sc[h * 4096 + base]);
            ex[h] = v.x; ey[h] = v.y;
            zx += v.x; zy += v.y;
        }
        float ix = POST_SCALE / zx, iy = POST_SCALE / zy;
#pragma unroll
        for (int h = 0; h < NHEAD; h++) {
            *(__half2*)(P + ((size_t)h * SEQ + s0 + s) * SEQ + t0 + 2 * tp) =
                __floats2half2_rn(ex[h] * ix, ey[h] * iy);
        }
    }
#undef LOAD_ST
#undef COMPUTE_ST
}

// ============================================================
// PV (R11 champion, unchanged): BM=128, BN=64, BK=64,
// 3-stage cp.async ring, 256 threads, 3 CTAs/SM hint.
// ============================================================
#define PV_STAGE 24576
#define PV_SMEM  (3 * PV_STAGE)

__global__ __launch_bounds__(256, 3) void pv16(
    const __half* __restrict__ P, const __half* __restrict__ V,
    __half* __restrict__ Y)
{
    extern __shared__ __align__(16) unsigned char pvsm[];
    const uint32_t smb = (uint32_t)__cvta_generic_to_shared(pvsm);
    const int tid = threadIdx.x, lane = tid & 31, warp = tid >> 5;
    const int wm = warp >> 1, wn = warp & 1;
    const int h = blockIdx.z;
    const int m0 = blockIdx.y * 128;
    const int g = lane >> 2, t4 = lane & 3;
    const __half* Ph = P + (size_t)h * SEQ * SEQ;

    float c[2][4][4];
#pragma unroll
    for (int mt = 0; mt < 2; mt++)
#pragma unroll
        for (int nt = 0; nt < 4; nt++)
#pragma unroll
            for (int r = 0; r < 4; r++) c[mt][nt][r] = 0.f;

#pragma unroll
    for (int st = 0; st < 2; st++) {
        int kt = st * 64;
        uint32_t ab = smb + st * PV_STAGE, bb = ab + 16384;
#pragma unroll
        for (int i = 0; i < 4; i++) {
            int op = tid + i * 256; int row = op >> 3, ch = op & 7;
            cp16(ab + swz(row, ch), Ph + (size_t)(m0 + row) * SEQ + kt + ch * 8);
        }
#pragma unroll
        for (int i = 0; i < 2; i++) {
            int op = tid + i * 256; int row = op >> 3, ch = op & 7;
            cp16(bb + swz(row, ch), V + (size_t)(kt + row) * DIM + h * DHEAD + ch * 8);
        }
        CP_COMMIT();
    }

    for (int it = 0; it < 64; it++) {
        int left = 63 - it;
        if (left >= 2) {
            int kt = (it + 2) * 64;
            uint32_t ab = smb + ((it + 2) % 3) * PV_STAGE, bb = ab + 16384;
#pragma unroll
            for (int i = 0; i < 4; i++) {
                int op = tid + i * 256; int row = op >> 3, ch = op & 7;
                cp16(ab + swz(row, ch), Ph + (size_t)(m0 + row) * SEQ + kt + ch * 8);
            }
#pragma unroll
            for (int i = 0; i < 2; i++) {
                int op = tid + i * 256; int row = op >> 3, ch = op & 7;
                cp16(bb + swz(row, ch), V + (size_t)(kt + row) * DIM + h * DHEAD + ch * 8);
            }
            CP_COMMIT();
            CP_WAIT2();
        } else if (left == 1) {
            CP_WAIT1();
        } else {
            CP_WAIT0();
        }
        __syncthreads();

        uint32_t ab = smb + (it % 3) * PV_STAGE, bb = ab + 16384;
#pragma unroll
        for (int ks = 0; ks < 4; ks++) {
            uint32_t a[2][4], b[2][4];
#pragma unroll
            for (int mt = 0; mt < 2; mt++) {
                int row = wm * 32 + mt * 16 + (lane & 15);
                int ch = ks * 2 + (lane >> 4);
                LDSM4(a[mt], ab + swz(row, ch));
            }
#pragma unroll
            for (int p = 0; p < 2; p++) {
                int row = ks * 16 + (lane & 15);
                int ch = wn * 4 + p * 2 + (lane >> 4);
                LDSM4T(b[p], bb + swz(row, ch));
            }
#pragma unroll
            for (int mt = 0; mt < 2; mt++) {
                mma16(c[mt][0], a[mt], &b[0][0]);
                mma16(c[mt][1], a[mt], &b[0][2]);
                mma16(c[mt][2], a[mt], &b[1][0]);
                mma16(c[mt][3], a[mt], &b[1][2]);
            }
        }
        __syncthreads();
    }

#pragma unroll
    for (int mt = 0; mt < 2; mt++)
#pragma unroll
        for (int nt = 0; nt < 4; nt++) {
            int col = h * DHEAD + wn * 32 + nt * 8 + t4 * 2;
#pragma unroll
            for (int rh = 0; rh < 2; rh++) {
                int row = m0 + wm * 32 + mt * 16 + g + rh * 8;
                *(__half2*)(Y + (size_t)row * DIM + col) =
                    __floats2half2_rn(c[mt][nt][rh * 2], c[mt][nt][rh * 2 + 1]);
            }
        }
}

// ============================================================
extern "C" void kernel_launch(void* const* d_in, const int* in_sizes, int n_in,
                              void* d_out, int out_size)
{
    const float* x  = (const float*)d_in[0];
    const float* Wq = (const float*)d_in[1];
    const float* bq = (const float*)d_in[2];
    const float* Wk = (const float*)d_in[3];
    const float* bk = (const float*)d_in[4];
    const float* Wv = (const float*)d_in[5];
    const float* bv = (const float*)d_in[6];
    const float* Wo = (const float*)d_in[7];
    const float* bo = (const float*)d_in[8];
    float* out = (float*)d_out;

    __half *x16, *wpk, *QKV, *Ah, *P;
    float* bqkv;
    cudaGetSymbolAddress((void**)&x16, g_x16);
    cudaGetSymbolAddress((void**)&wpk, g_w);
    cudaGetSymbolAddress((void**)&bqkv, g_bqkv);
    cudaGetSymbolAddress((void**)&QKV, g_QKV);
    cudaGetSymbolAddress((void**)&Ah, g_Ah);
    cudaGetSymbolAddress((void**)&P, g_P);

    cudaFuncSetAttribute(scores16, cudaFuncAttributeMaxDynamicSharedMemorySize, SC_SMEM);
    cudaFuncSetAttribute(pv16,     cudaFuncAttributeMaxDynamicSharedMemorySize, PV_SMEM);
    cudaFuncSetAttribute(linear128<true>,
                         cudaFuncAttributeMaxDynamicSharedMemorySize, LN_SMEM);
    cudaFuncSetAttribute(linear128<false>,
                         cudaFuncAttributeMaxDynamicSharedMemorySize, LN_SMEM);

    cvt_all<<<2048, 256>>>(x, Wq, Wk, Wv, Wo, bq, bk, bv, x16, wpk, bqkv);

    dim3 gqkv(3 * DIM / 128, SEQ / 128);
    linear128<true><<<gqkv, 256, LN_SMEM>>>(x16, wpk, bqkv, QKV);

    const __half* Qh = QKV;
    const __half* Kh = QKV + (size_t)SEQ * DIM;
    const __half* Vh = QKV + (size_t)2 * SEQ * DIM;

    dim3 gsc(SEQ / 64, SEQ / 64);
    scores16<<<gsc, 512, SC_SMEM>>>(Qh, Kh, P);

    dim3 gpv(1, SEQ / 128, NHEAD);
    pv16<<<gpv, 256, PV_SMEM>>>(P, Vh, Ah);

    dim3 glin(DIM / 128, SEQ / 128);
    linear128<false><<<glin, 256, LN_SMEM>>>(Ah, wpk + (size_t)3 * DIM * DIM, bo, out);
}